// round 6
// baseline (speedup 1.0000x reference)
#include <cuda_runtime.h>
#include <cstdint>

#define MAX_NODES 100000
#define D 64
#define CAP 64
#define OVFCAP 8192

// ---------------- scratch (device globals: no allocation allowed) ----------
__device__ float g_pre_dst[(size_t)MAX_NODES * D];  // x@W1a + (u@W1d + b1)[batch]
__device__ float g_pre_src[(size_t)MAX_NODES * D];  // x@W1b
__device__ float g_agg[(size_t)MAX_NODES * D];      // per-node message sums
__device__ float g_ugb[16 * D];                     // u@W1d + b1 per graph
__device__ float g_uc2[16 * D];                     // u@W2c + b2 per graph
__device__ int   g_deg[MAX_NODES];
__device__ unsigned long long g_bucket[(size_t)MAX_NODES * CAP];  // (eid<<32)|src
__device__ int   g_ovf_cnt;
__device__ unsigned long long g_ovf_pair[OVFCAP];
__device__ int   g_ovf_dst[OVFCAP];

// ---------------- packed f32x2 helpers (Blackwell FFMA2) -------------------
__device__ __forceinline__ unsigned long long fma2(unsigned long long a,
                                                   unsigned long long b,
                                                   unsigned long long c) {
    unsigned long long d;
    asm("fma.rn.f32x2 %0, %1, %2, %3;" : "=l"(d) : "l"(a), "l"(b), "l"(c));
    return d;
}
__device__ __forceinline__ unsigned long long pack2(float x, float y) {
    unsigned long long r;
    asm("mov.b64 %0, {%1, %2};" : "=l"(r) : "f"(x), "f"(y));
    return r;
}
__device__ __forceinline__ float2 unpack2(unsigned long long v) {
    float2 r;
    asm("mov.b64 {%0, %1}, %2;" : "=f"(r.x), "=f"(r.y) : "l"(v));
    return r;
}

// ---------------- K0: zero deg/ovf + per-graph tables -----------------------
__global__ void init_k(const float* __restrict__ u,
                       const float* __restrict__ W1, const float* __restrict__ b1,
                       const float* __restrict__ W2, const float* __restrict__ b2,
                       int N) {
    int i = blockIdx.x * blockDim.x + threadIdx.x;
    if (i < N) g_deg[i] = 0;
    if (i == 0) g_ovf_cnt = 0;
    if (blockIdx.x == 0) {  // 1024 threads = 16 graphs x 64 cols
        int j = threadIdx.x & 63;
        int g = threadIdx.x >> 6;
        float s1 = b1[j], s2 = b2[j];
#pragma unroll
        for (int k = 0; k < 32; k++) {
            float uv = u[g * 32 + k];
            s1 += uv * W1[(160 + k) * 64 + j];
            s2 += uv * W2[(128 + k) * 64 + j];
        }
        g_ugb[g * 64 + j] = s1;
        g_uc2[g * 64 + j] = s2;
    }
}

// ---------------- CSR-bucket fill --------------------------------------------
__global__ void fill_k(const int* __restrict__ ei, int E) {
    int e = blockIdx.x * blockDim.x + threadIdx.x;
    if (e >= E) return;
    int src = __ldg(ei + e);
    int dst = __ldg(ei + E + e);
    int pos = atomicAdd(&g_deg[dst], 1);
    unsigned long long pr = ((unsigned long long)(unsigned)e << 32) | (unsigned)src;
    if (pos < CAP) {
        g_bucket[(size_t)dst * CAP + pos] = pr;
    } else {
        int oi = atomicAdd(&g_ovf_cnt, 1);
        if (oi < OVFCAP) { g_ovf_pair[oi] = pr; g_ovf_dst[oi] = dst; }
    }
}

// ---------------- fused node pre-GEMM ---------------------------------------
__global__ __launch_bounds__(256) void node_pre(
    const float* __restrict__ x, const float* __restrict__ W1,
    const float* __restrict__ ugb, const int* __restrict__ batch, int N) {
    __shared__ float sXT[64][68];
    __shared__ float sW[64][64];
    const int tid = threadIdx.x;
    const int tn = tid & 15;
    const int tj = tid >> 4;
    const int node0 = blockIdx.x * 64;

    for (int i = tid; i < 4096; i += 256) {
        int r = i >> 6, c = i & 63;
        int n = node0 + r;
        sXT[c][r] = (n < N) ? x[(size_t)n * 64 + c] : 0.f;
    }

    unsigned long long acc[2][4][2];
#pragma unroll
    for (int a = 0; a < 2; a++)
#pragma unroll
        for (int i = 0; i < 4; i++) { acc[a][i][0] = 0ull; acc[a][i][1] = 0ull; }

    for (int a = 0; a < 2; a++) {
        __syncthreads();
        for (int i = tid; i < 4096; i += 256) {
            int k = i >> 6, j = i & 63;
            sW[k][j] = W1[(size_t)(a * 64 + k) * 64 + j];
        }
        __syncthreads();
#pragma unroll 8
        for (int k = 0; k < 64; k++) {
            float4 xv = *reinterpret_cast<const float4*>(&sXT[k][tn * 4]);
            ulonglong2 wv = *reinterpret_cast<const ulonglong2*>(&sW[k][tj * 4]);
            unsigned long long xd;
            xd = pack2(xv.x, xv.x);
            acc[a][0][0] = fma2(xd, wv.x, acc[a][0][0]); acc[a][0][1] = fma2(xd, wv.y, acc[a][0][1]);
            xd = pack2(xv.y, xv.y);
            acc[a][1][0] = fma2(xd, wv.x, acc[a][1][0]); acc[a][1][1] = fma2(xd, wv.y, acc[a][1][1]);
            xd = pack2(xv.z, xv.z);
            acc[a][2][0] = fma2(xd, wv.x, acc[a][2][0]); acc[a][2][1] = fma2(xd, wv.y, acc[a][2][1]);
            xd = pack2(xv.w, xv.w);
            acc[a][3][0] = fma2(xd, wv.x, acc[a][3][0]); acc[a][3][1] = fma2(xd, wv.y, acc[a][3][1]);
        }
    }

#pragma unroll
    for (int nn = 0; nn < 4; nn++) {
        int n = node0 + tn * 4 + nn;
        if (n < N) {
            float2 p0 = unpack2(acc[0][nn][0]);
            float2 p1 = unpack2(acc[0][nn][1]);
            int g = __ldg(batch + n);
            float4 tv = *reinterpret_cast<const float4*>(ugb + g * 64 + tj * 4);
            float4 o = make_float4(p0.x + tv.x, p0.y + tv.y, p1.x + tv.z, p1.y + tv.w);
            *reinterpret_cast<float4*>(g_pre_dst + (size_t)n * 64 + tj * 4) = o;
            p0 = unpack2(acc[1][nn][0]);
            p1 = unpack2(acc[1][nn][1]);
            float4 o2 = make_float4(p0.x, p0.y, p1.x, p1.y);
            *reinterpret_cast<float4*>(g_pre_src + (size_t)n * 64 + tj * 4) = o2;
        }
    }
}

// ---------------- gather: per-node edge MLP + register reduction ------------
// One warp per node (strided). Lane l owns output cols (2l, 2l+1).
// W1c block (rows 128..159) lives in registers. No atomics: one coalesced
// 256B store per node.
__global__ __launch_bounds__(256) void gather_k(
    const float* __restrict__ ea, const float* __restrict__ W1, int N) {
    const float* __restrict__ Wc = W1 + 128 * 64;
    const int lane = threadIdx.x & 31;
    const int c0 = 2 * lane;

    unsigned long long wA[16], wB[16];
#pragma unroll
    for (int kp = 0; kp < 16; kp++) {
        wA[kp] = pack2(__ldg(Wc + (2 * kp) * 64 + c0),
                       __ldg(Wc + (2 * kp + 1) * 64 + c0));
        wB[kp] = pack2(__ldg(Wc + (2 * kp) * 64 + c0 + 1),
                       __ldg(Wc + (2 * kp + 1) * 64 + c0 + 1));
    }

    const int warp = (blockIdx.x * blockDim.x + threadIdx.x) >> 5;
    const int nw = (gridDim.x * blockDim.x) >> 5;

    for (int n = warp; n < N; n += nw) {
        int deg = __ldg(&g_deg[n]);
        if (deg > CAP) deg = CAP;
        float s0 = 0.f, s1 = 0.f;
        if (deg > 0) {
            float2 pd = __ldg(reinterpret_cast<const float2*>(g_pre_dst + (size_t)n * 64) + lane);
            const unsigned long long* __restrict__ bp = g_bucket + (size_t)n * CAP;
            unsigned long long pr = __ldg(bp);
            for (int i = 0; i < deg; i++) {
                // prefetch next bucket entry to break the dependent chain
                unsigned long long prn = (i + 1 < deg) ? __ldg(bp + i + 1) : 0ull;
                int src = (int)(unsigned)pr;
                int eid = (int)(unsigned)(pr >> 32);
                float2 ps = __ldg(reinterpret_cast<const float2*>(g_pre_src + (size_t)src * 64) + lane);
                const ulonglong2* __restrict__ eap =
                    reinterpret_cast<const ulonglong2*>(ea) + (size_t)eid * 8;
                ulonglong2 ev[8];
#pragma unroll
                for (int q = 0; q < 8; q++) ev[q] = __ldg(eap + q);
                unsigned long long accA = 0ull, accB = 0ull;
#pragma unroll
                for (int q = 0; q < 8; q++) {
                    accA = fma2(ev[q].x, wA[2 * q], accA);
                    accA = fma2(ev[q].y, wA[2 * q + 1], accA);
                    accB = fma2(ev[q].x, wB[2 * q], accB);
                    accB = fma2(ev[q].y, wB[2 * q + 1], accB);
                }
                float2 a2 = unpack2(accA);
                float2 b2 = unpack2(accB);
                s0 += fmaxf(a2.x + a2.y + pd.x + ps.x, 0.f);
                s1 += fmaxf(b2.x + b2.y + pd.y + ps.y, 0.f);
                pr = prn;
            }
        }
        *reinterpret_cast<float2*>(g_agg + (size_t)n * 64 + c0) = make_float2(s0, s1);
    }
}

// ---------------- overflow fixup (normally 0 edges) --------------------------
__global__ __launch_bounds__(256) void ovf_k(
    const float* __restrict__ ea, const float* __restrict__ W1) {
    int cnt = g_ovf_cnt;
    if (cnt <= 0) return;
    if (cnt > OVFCAP) cnt = OVFCAP;
    const float* __restrict__ Wc = W1 + 128 * 64;
    const int lane = threadIdx.x & 31;
    const int c0 = 2 * lane;
    unsigned long long wA[16], wB[16];
#pragma unroll
    for (int kp = 0; kp < 16; kp++) {
        wA[kp] = pack2(__ldg(Wc + (2 * kp) * 64 + c0),
                       __ldg(Wc + (2 * kp + 1) * 64 + c0));
        wB[kp] = pack2(__ldg(Wc + (2 * kp) * 64 + c0 + 1),
                       __ldg(Wc + (2 * kp + 1) * 64 + c0 + 1));
    }
    const int warp = (blockIdx.x * blockDim.x + threadIdx.x) >> 5;
    const int nw = (gridDim.x * blockDim.x) >> 5;
    for (int i = warp; i < cnt; i += nw) {
        unsigned long long pr = g_ovf_pair[i];
        int dst = g_ovf_dst[i];
        int src = (int)(unsigned)pr;
        int eid = (int)(unsigned)(pr >> 32);
        float2 pd = __ldg(reinterpret_cast<const float2*>(g_pre_dst + (size_t)dst * 64) + lane);
        float2 ps = __ldg(reinterpret_cast<const float2*>(g_pre_src + (size_t)src * 64) + lane);
        const ulonglong2* __restrict__ eap =
            reinterpret_cast<const ulonglong2*>(ea) + (size_t)eid * 8;
        unsigned long long accA = 0ull, accB = 0ull;
#pragma unroll
        for (int q = 0; q < 8; q++) {
            ulonglong2 ev = __ldg(eap + q);
            accA = fma2(ev.x, wA[2 * q], accA);
            accA = fma2(ev.y, wA[2 * q + 1], accA);
            accB = fma2(ev.x, wB[2 * q], accB);
            accB = fma2(ev.y, wB[2 * q + 1], accB);
        }
        float2 a2 = unpack2(accA);
        float2 b2 = unpack2(accB);
        float v0 = fmaxf(a2.x + a2.y + pd.x + ps.x, 0.f);
        float v1 = fmaxf(b2.x + b2.y + pd.y + ps.y, 0.f);
        atomicAdd(g_agg + (size_t)dst * 64 + c0, v0);
        atomicAdd(g_agg + (size_t)dst * 64 + c0 + 1, v1);
    }
}

// ---------------- final node GEMM --------------------------------------------
__global__ __launch_bounds__(256) void dense_final(
    const float* __restrict__ x, const float* __restrict__ W2,
    const float* __restrict__ uc2, const int* __restrict__ batch,
    float* __restrict__ out, int N) {
    __shared__ float sXT[64][68];
    __shared__ float sW[64][64];
    const int tid = threadIdx.x;
    const int tn = tid & 15;
    const int tj = tid >> 4;
    const int node0 = blockIdx.x * 64;

    unsigned long long acc[4][2];
#pragma unroll
    for (int i = 0; i < 4; i++) { acc[i][0] = 0ull; acc[i][1] = 0ull; }

    for (int a = 0; a < 2; a++) {
        const float* __restrict__ A = (a == 0) ? x : g_agg;
        for (int i = tid; i < 4096; i += 256) {
            int r = i >> 6, c = i & 63;
            int n = node0 + r;
            sXT[c][r] = (n < N) ? A[(size_t)n * 64 + c] : 0.f;
        }
        for (int i = tid; i < 4096; i += 256) {
            int k = i >> 6, j = i & 63;
            sW[k][j] = W2[(size_t)(a * 64 + k) * 64 + j];
        }
        __syncthreads();
#pragma unroll 8
        for (int k = 0; k < 64; k++) {
            float4 xv = *reinterpret_cast<const float4*>(&sXT[k][tn * 4]);
            ulonglong2 wv = *reinterpret_cast<const ulonglong2*>(&sW[k][tj * 4]);
            unsigned long long xd;
            xd = pack2(xv.x, xv.x);
            acc[0][0] = fma2(xd, wv.x, acc[0][0]); acc[0][1] = fma2(xd, wv.y, acc[0][1]);
            xd = pack2(xv.y, xv.y);
            acc[1][0] = fma2(xd, wv.x, acc[1][0]); acc[1][1] = fma2(xd, wv.y, acc[1][1]);
            xd = pack2(xv.z, xv.z);
            acc[2][0] = fma2(xd, wv.x, acc[2][0]); acc[2][1] = fma2(xd, wv.y, acc[2][1]);
            xd = pack2(xv.w, xv.w);
            acc[3][0] = fma2(xd, wv.x, acc[3][0]); acc[3][1] = fma2(xd, wv.y, acc[3][1]);
        }
        __syncthreads();
    }

#pragma unroll
    for (int nn = 0; nn < 4; nn++) {
        int n = node0 + tn * 4 + nn;
        if (n < N) {
            float2 p0 = unpack2(acc[nn][0]);
            float2 p1 = unpack2(acc[nn][1]);
            int g = __ldg(batch + n);
            float4 tv = *reinterpret_cast<const float4*>(uc2 + g * 64 + tj * 4);
            float4 o = make_float4(fmaxf(p0.x + tv.x, 0.f), fmaxf(p0.y + tv.y, 0.f),
                                   fmaxf(p1.x + tv.z, 0.f), fmaxf(p1.y + tv.w, 0.f));
            *reinterpret_cast<float4*>(out + (size_t)n * 64 + tj * 4) = o;
        }
    }
}

// ---------------- launch ------------------------------------------------------
extern "C" void kernel_launch(void* const* d_in, const int* in_sizes, int n_in,
                              void* d_out, int out_size) {
    const float* x     = (const float*)d_in[0];
    const int*   ei    = (const int*)d_in[1];
    const float* ea    = (const float*)d_in[2];
    const float* u     = (const float*)d_in[3];
    const int*   batch = (const int*)d_in[4];
    const float* W1    = (const float*)d_in[5];
    const float* b1    = (const float*)d_in[6];
    const float* W2    = (const float*)d_in[7];
    const float* b2    = (const float*)d_in[8];
    float* out = (float*)d_out;

    const int N = in_sizes[0] / 64;   // 100000
    const int E = in_sizes[2] / 32;   // 1000000

    float *ugb, *uc2;
    cudaGetSymbolAddress((void**)&ugb, g_ugb);
    cudaGetSymbolAddress((void**)&uc2, g_uc2);

    // 0: zero deg/ovf + per-graph tables
    init_k<<<(N + 1023) / 1024, 1024>>>(u, W1, b1, W2, b2, N);
    // 1: build per-dst edge buckets
    fill_k<<<(E + 255) / 256, 256>>>(ei, E);
    // 2: fused pre_dst + pre_src
    node_pre<<<(N + 63) / 64, 256>>>(x, W1, ugb, batch, N);
    // 3: gather + edge MLP + register reduction  <-- ncu capture index
    gather_k<<<2048, 256>>>(ea, W1, N);
    // 4: overflow fixup (statistically empty)
    ovf_k<<<8, 256>>>(ea, W1);
    // 5: final node MLP
    dense_final<<<(N + 63) / 64, 256>>>(x, W2, uc2, batch, out, N);
}

// round 7
// speedup vs baseline: 1.6546x; 1.6546x over previous
#include <cuda_runtime.h>
#include <cstdint>

#define MAX_NODES 100000
#define D 64

// ---------------- scratch (device globals: no allocation allowed) ----------
__device__ float g_pre_dst[(size_t)MAX_NODES * D];  // x@W1a + (u@W1d + b1)[batch]
__device__ float g_pre_src[(size_t)MAX_NODES * D];  // x@W1b
__device__ float g_agg[(size_t)MAX_NODES * D];      // scatter-sum target
__device__ float g_ugb[16 * D];                     // u@W1d + b1 per graph
__device__ float g_uc2[16 * D];                     // u@W2c + b2 per graph

// ---------------- packed f32x2 helpers (Blackwell FFMA2) -------------------
__device__ __forceinline__ unsigned long long fma2(unsigned long long a,
                                                   unsigned long long b,
                                                   unsigned long long c) {
    unsigned long long d;
    asm("fma.rn.f32x2 %0, %1, %2, %3;" : "=l"(d) : "l"(a), "l"(b), "l"(c));
    return d;
}
__device__ __forceinline__ unsigned long long pack2(float x, float y) {
    unsigned long long r;
    asm("mov.b64 %0, {%1, %2};" : "=l"(r) : "f"(x), "f"(y));
    return r;
}
__device__ __forceinline__ float2 unpack2(unsigned long long v) {
    float2 r;
    asm("mov.b64 {%0, %1}, %2;" : "=f"(r.x), "=f"(r.y) : "l"(v));
    return r;
}

// ---------------- noop: shifts ncu capture slot -----------------------------
__global__ void noop_k() {}

// ---------------- per-graph tables ------------------------------------------
__global__ void init_k(const float* __restrict__ u,
                       const float* __restrict__ W1, const float* __restrict__ b1,
                       const float* __restrict__ W2, const float* __restrict__ b2) {
    int j = threadIdx.x & 63;
    int g = threadIdx.x >> 6;   // 1024 threads = 16 graphs x 64 cols
    float s1 = b1[j], s2 = b2[j];
#pragma unroll
    for (int k = 0; k < 32; k++) {
        float uv = u[g * 32 + k];
        s1 += uv * W1[(160 + k) * 64 + j];
        s2 += uv * W2[(128 + k) * 64 + j];
    }
    g_ugb[g * 64 + j] = s1;
    g_uc2[g * 64 + j] = s2;
}

// ---------------- fused node pre-GEMM (also zeroes g_agg) -------------------
__global__ __launch_bounds__(256) void node_pre(
    const float* __restrict__ x, const float* __restrict__ W1,
    const float* __restrict__ ugb, const int* __restrict__ batch, int N) {
    __shared__ float sXT[64][68];
    __shared__ float sW[64][64];
    const int tid = threadIdx.x;
    const int tn = tid & 15;
    const int tj = tid >> 4;
    const int node0 = blockIdx.x * 64;

    // zero this block's slice of g_agg (16 float4 per thread = 64x64 floats)
    {
        float4* ap = reinterpret_cast<float4*>(g_agg + (size_t)node0 * 64);
        int limit = (N - node0) * 16;          // float4s in this block's slice
        if (limit > 1024) limit = 1024;
        for (int i = tid; i < limit; i += 256)
            ap[i] = make_float4(0.f, 0.f, 0.f, 0.f);
    }

    for (int i = tid; i < 4096; i += 256) {
        int r = i >> 6, c = i & 63;
        int n = node0 + r;
        sXT[c][r] = (n < N) ? x[(size_t)n * 64 + c] : 0.f;
    }

    unsigned long long acc[2][4][2];
#pragma unroll
    for (int a = 0; a < 2; a++)
#pragma unroll
        for (int i = 0; i < 4; i++) { acc[a][i][0] = 0ull; acc[a][i][1] = 0ull; }

    for (int a = 0; a < 2; a++) {
        __syncthreads();
        for (int i = tid; i < 4096; i += 256) {
            int k = i >> 6, j = i & 63;
            sW[k][j] = W1[(size_t)(a * 64 + k) * 64 + j];
        }
        __syncthreads();
#pragma unroll 8
        for (int k = 0; k < 64; k++) {
            float4 xv = *reinterpret_cast<const float4*>(&sXT[k][tn * 4]);
            ulonglong2 wv = *reinterpret_cast<const ulonglong2*>(&sW[k][tj * 4]);
            unsigned long long xd;
            xd = pack2(xv.x, xv.x);
            acc[a][0][0] = fma2(xd, wv.x, acc[a][0][0]); acc[a][0][1] = fma2(xd, wv.y, acc[a][0][1]);
            xd = pack2(xv.y, xv.y);
            acc[a][1][0] = fma2(xd, wv.x, acc[a][1][0]); acc[a][1][1] = fma2(xd, wv.y, acc[a][1][1]);
            xd = pack2(xv.z, xv.z);
            acc[a][2][0] = fma2(xd, wv.x, acc[a][2][0]); acc[a][2][1] = fma2(xd, wv.y, acc[a][2][1]);
            xd = pack2(xv.w, xv.w);
            acc[a][3][0] = fma2(xd, wv.x, acc[a][3][0]); acc[a][3][1] = fma2(xd, wv.y, acc[a][3][1]);
        }
    }

#pragma unroll
    for (int nn = 0; nn < 4; nn++) {
        int n = node0 + tn * 4 + nn;
        if (n < N) {
            float2 p0 = unpack2(acc[0][nn][0]);
            float2 p1 = unpack2(acc[0][nn][1]);
            int g = __ldg(batch + n);
            float4 tv = *reinterpret_cast<const float4*>(ugb + g * 64 + tj * 4);
            float4 o = make_float4(p0.x + tv.x, p0.y + tv.y, p1.x + tv.z, p1.y + tv.w);
            *reinterpret_cast<float4*>(g_pre_dst + (size_t)n * 64 + tj * 4) = o;
            p0 = unpack2(acc[1][nn][0]);
            p1 = unpack2(acc[1][nn][1]);
            float4 o2 = make_float4(p0.x, p0.y, p1.x, p1.y);
            *reinterpret_cast<float4*>(g_pre_src + (size_t)n * 64 + tj * 4) = o2;
        }
    }
}

// ---------------- edge kernel ------------------------------------------------
// One warp per edge, grid-stride, software-pipelined index prefetch.
// blockDim=128, 4 CTAs/SM (reg cap 128) -> 16 warps/SM for latency hiding.
__global__ __launch_bounds__(128, 4) void edge_kernel(
    const int* __restrict__ ei, const float* __restrict__ ea,
    const float* __restrict__ W1, int E) {
    const float* __restrict__ Wc = W1 + 128 * 64;
    const int lane = threadIdx.x & 31;
    const int c0 = 2 * lane;

    unsigned long long wA[16], wB[16];
#pragma unroll
    for (int kp = 0; kp < 16; kp++) {
        wA[kp] = pack2(__ldg(Wc + (2 * kp) * 64 + c0),
                       __ldg(Wc + (2 * kp + 1) * 64 + c0));
        wB[kp] = pack2(__ldg(Wc + (2 * kp) * 64 + c0 + 1),
                       __ldg(Wc + (2 * kp + 1) * 64 + c0 + 1));
    }

    const int warp = (blockIdx.x * blockDim.x + threadIdx.x) >> 5;
    const int nw = (gridDim.x * blockDim.x) >> 5;

    int e = warp;
    if (e >= E) return;
    int src = __ldg(ei + e);
    int dst = __ldg(ei + E + e);

    while (true) {
        const int en = e + nw;
        const bool more = (en < E);
        int srcn = 0, dstn = 0;
        if (more) { srcn = __ldg(ei + en); dstn = __ldg(ei + E + en); }

        float2 pd = __ldg(reinterpret_cast<const float2*>(g_pre_dst + (size_t)dst * 64) + lane);
        float2 ps = __ldg(reinterpret_cast<const float2*>(g_pre_src + (size_t)src * 64) + lane);

        const ulonglong2* __restrict__ eap =
            reinterpret_cast<const ulonglong2*>(ea) + (size_t)e * 8;
        ulonglong2 ev[8];
#pragma unroll
        for (int q = 0; q < 8; q++) ev[q] = __ldg(eap + q);

        unsigned long long accA = 0ull, accB = 0ull;
#pragma unroll
        for (int q = 0; q < 8; q++) {
            accA = fma2(ev[q].x, wA[2 * q], accA);
            accA = fma2(ev[q].y, wA[2 * q + 1], accA);
            accB = fma2(ev[q].x, wB[2 * q], accB);
            accB = fma2(ev[q].y, wB[2 * q + 1], accB);
        }

        float2 a2 = unpack2(accA);
        float2 b2 = unpack2(accB);
        float v0 = fmaxf(a2.x + a2.y + pd.x + ps.x, 0.f);
        float v1 = fmaxf(b2.x + b2.y + pd.y + ps.y, 0.f);

        float w0 = __shfl_xor_sync(0xffffffffu, v0, 1);
        float w1 = __shfl_xor_sync(0xffffffffu, v1, 1);
        if (!(lane & 1)) {
            if ((v0 != 0.f) || (v1 != 0.f) || (w0 != 0.f) || (w1 != 0.f)) {
                float* ap = g_agg + (size_t)dst * 64 + c0;
                asm volatile("red.global.add.v4.f32 [%0], {%1, %2, %3, %4};"
                             :: "l"(ap), "f"(v0), "f"(v1), "f"(w0), "f"(w1)
                             : "memory");
            }
        }

        if (!more) break;
        e = en; src = srcn; dst = dstn;
    }
}

// ---------------- final node GEMM --------------------------------------------
__global__ __launch_bounds__(256) void dense_final(
    const float* __restrict__ x, const float* __restrict__ W2,
    const float* __restrict__ uc2, const int* __restrict__ batch,
    float* __restrict__ out, int N) {
    __shared__ float sXT[64][68];
    __shared__ float sW[64][64];
    const int tid = threadIdx.x;
    const int tn = tid & 15;
    const int tj = tid >> 4;
    const int node0 = blockIdx.x * 64;

    unsigned long long acc[4][2];
#pragma unroll
    for (int i = 0; i < 4; i++) { acc[i][0] = 0ull; acc[i][1] = 0ull; }

    for (int a = 0; a < 2; a++) {
        const float* __restrict__ A = (a == 0) ? x : g_agg;
        for (int i = tid; i < 4096; i += 256) {
            int r = i >> 6, c = i & 63;
            int n = node0 + r;
            sXT[c][r] = (n < N) ? A[(size_t)n * 64 + c] : 0.f;
        }
        for (int i = tid; i < 4096; i += 256) {
            int k = i >> 6, j = i & 63;
            sW[k][j] = W2[(size_t)(a * 64 + k) * 64 + j];
        }
        __syncthreads();
#pragma unroll 8
        for (int k = 0; k < 64; k++) {
            float4 xv = *reinterpret_cast<const float4*>(&sXT[k][tn * 4]);
            ulonglong2 wv = *reinterpret_cast<const ulonglong2*>(&sW[k][tj * 4]);
            unsigned long long xd;
            xd = pack2(xv.x, xv.x);
            acc[0][0] = fma2(xd, wv.x, acc[0][0]); acc[0][1] = fma2(xd, wv.y, acc[0][1]);
            xd = pack2(xv.y, xv.y);
            acc[1][0] = fma2(xd, wv.x, acc[1][0]); acc[1][1] = fma2(xd, wv.y, acc[1][1]);
            xd = pack2(xv.z, xv.z);
            acc[2][0] = fma2(xd, wv.x, acc[2][0]); acc[2][1] = fma2(xd, wv.y, acc[2][1]);
            xd = pack2(xv.w, xv.w);
            acc[3][0] = fma2(xd, wv.x, acc[3][0]); acc[3][1] = fma2(xd, wv.y, acc[3][1]);
        }
        __syncthreads();
    }

#pragma unroll
    for (int nn = 0; nn < 4; nn++) {
        int n = node0 + tn * 4 + nn;
        if (n < N) {
            float2 p0 = unpack2(acc[nn][0]);
            float2 p1 = unpack2(acc[nn][1]);
            int g = __ldg(batch + n);
            float4 tv = *reinterpret_cast<const float4*>(uc2 + g * 64 + tj * 4);
            float4 o = make_float4(fmaxf(p0.x + tv.x, 0.f), fmaxf(p0.y + tv.y, 0.f),
                                   fmaxf(p1.x + tv.z, 0.f), fmaxf(p1.y + tv.w, 0.f));
            *reinterpret_cast<float4*>(out + (size_t)n * 64 + tj * 4) = o;
        }
    }
}

// ---------------- launch ------------------------------------------------------
extern "C" void kernel_launch(void* const* d_in, const int* in_sizes, int n_in,
                              void* d_out, int out_size) {
    const float* x     = (const float*)d_in[0];
    const int*   ei    = (const int*)d_in[1];
    const float* ea    = (const float*)d_in[2];
    const float* u     = (const float*)d_in[3];
    const int*   batch = (const int*)d_in[4];
    const float* W1    = (const float*)d_in[5];
    const float* b1    = (const float*)d_in[6];
    const float* W2    = (const float*)d_in[7];
    const float* b2    = (const float*)d_in[8];
    float* out = (float*)d_out;

    const int N = in_sizes[0] / 64;   // 100000
    const int E = in_sizes[2] / 32;   // 1000000

    float *ugb, *uc2;
    cudaGetSymbolAddress((void**)&ugb, g_ugb);
    cudaGetSymbolAddress((void**)&uc2, g_uc2);

    // 0: per-graph tables
    init_k<<<1, 1024>>>(u, W1, b1, W2, b2);
    // 1: fused pre_dst + pre_src (+ zero g_agg)
    node_pre<<<(N + 63) / 64, 256>>>(x, W1, ugb, batch, N);
    // 2: noop so the edge kernel lands at ncu capture slot 3
    noop_k<<<1, 32>>>();
    // 3: edge messages + scatter-sum  <-- ncu capture index
    edge_kernel<<<592, 128>>>(ei, ea, W1, E);
    // 4: final node MLP
    dense_final<<<(N + 63) / 64, 256>>>(x, W2, uc2, batch, out, N);
}